// round 14
// baseline (speedup 1.0000x reference)
#include <cuda_runtime.h>
#include <cuda_fp16.h>
#include <cstdint>

// Problem constants
constexpr int Bc = 8, Lc = 4096;
constexpr int Mrows = Bc * Lc;          // 32768
constexpr int NCHUNK = 64, CLEN = 64;   // 64 chunks of 64 steps

// Scratch (static device arrays -- no allocation allowed)
__device__ __half g_uh [(size_t)Mrows * 256]; // u  (fp16): [bl][h]
__device__ __half g_fh [(size_t)Mrows * 512]; // f  (fp16): [bl][2p+c]
__device__ __half g_ysh[(size_t)Mrows * 512]; // ys (fp16), same layout
__device__ __half g_BopH[512 * 256];          // GEMM1 B, [n=2p+c][k=h]
__device__ __half g_CopH[256 * 512];          // GEMM2 B, [n=h][k=2p+c]
__device__ float  g_m11[256], g_m12[256], g_dts[256];
__device__ float  g_cf  [Bc * 256 * NCHUNK * 4]; // [b][p][ch] float4
__device__ float  g_init[Bc * 256 * NCHUNK * 4];

__device__ __forceinline__ void cp_async16(void* smem, const void* gmem) {
    uint32_t s = (uint32_t)__cvta_generic_to_shared(smem);
    asm volatile("cp.async.ca.shared.global [%0], [%1], 16;\n" :: "r"(s), "l"(gmem));
}

__device__ __forceinline__ void mma_f16(float c[4], const uint32_t a[4], const uint32_t b[2]) {
    asm volatile(
        "mma.sync.aligned.m16n8k16.row.col.f32.f16.f16.f32 "
        "{%0,%1,%2,%3}, {%4,%5,%6,%7}, {%8,%9}, {%0,%1,%2,%3};\n"
        : "+f"(c[0]), "+f"(c[1]), "+f"(c[2]), "+f"(c[3])
        : "r"(a[0]), "r"(a[1]), "r"(a[2]), "r"(a[3]), "r"(b[0]), "r"(b[1]));
}

// ---------------------------------------------------------------------------
// u -> fp16 pre-pass: 8M floats, 8 per thread
// ---------------------------------------------------------------------------
__global__ void u2h_kernel(const float* __restrict__ U) {
    size_t i = ((size_t)blockIdx.x * 256 + threadIdx.x) * 8;
    float4 a = *reinterpret_cast<const float4*>(U + i);
    float4 b = *reinterpret_cast<const float4*>(U + i + 4);
    __half2 h0 = __floats2half2_rn(a.x, a.y);
    __half2 h1 = __floats2half2_rn(a.z, a.w);
    __half2 h2 = __floats2half2_rn(b.x, b.y);
    __half2 h3 = __floats2half2_rn(b.z, b.w);
    uint4 pk;
    pk.x = *reinterpret_cast<uint32_t*>(&h0);
    pk.y = *reinterpret_cast<uint32_t*>(&h1);
    pk.z = *reinterpret_cast<uint32_t*>(&h2);
    pk.w = *reinterpret_cast<uint32_t*>(&h3);
    *reinterpret_cast<uint4*>(g_uh + i) = pk;
}

// ---------------------------------------------------------------------------
// Prep: per-p recurrence params + fp16 operand matrices (B stored [n][k])
// ---------------------------------------------------------------------------
__global__ void prep_kernel(const float* __restrict__ Ad, const float* __restrict__ Gd,
                            const float* __restrict__ dt, const float* __restrict__ Bm,
                            const float* __restrict__ Cm) {
    int h = blockIdx.x;          // 0..255
    int n = threadIdx.x;         // 0..511
    int p = n >> 1;
    int c = n & 1;
    float dts = 1.0f / (1.0f + expf(-dt[p]));
    float G = fmaxf(Gd[p], dts * Ad[p]);
    float A = fmaxf(Ad[p], 0.25f * G * G);

    g_BopH[n * 256 + h] = __float2half(dts * Bm[p * 512 + h * 2 + c]);
    float cv = Cm[h * 512 + p * 2 + c];
    g_CopH[h * 512 + n] = __float2half(c ? -cv : cv);

    if (h == 0 && c == 0) {
        g_m11[p] = 1.0f - dts * G;
        g_m12[p] = -dts * A;
        g_dts[p] = dts;          // m21; m22 == 1
    }
}

// ---------------------------------------------------------------------------
// GEMM1 (+ fused local scan): f = u @ Bop^T  (M=32768, N=512, K=256)
// Both operands fp16 via cp.async. Epilogue: f fp16 + local scans -> g_cf.
// ---------------------------------------------------------------------------
__global__ void __launch_bounds__(256, 2)
gemm1_f16(const __half* __restrict__ AH, const __half* __restrict__ BmH,
          __half* __restrict__ F) {
    constexpr int N = 512, K = 256, nk = K / 32;
    extern __shared__ __half smh[];
    __half* As = smh;                 // 2 stages * 128*40
    __half* Bs = smh + 2 * 5120;

    const int tid  = threadIdx.x;
    const int lane = tid & 31, warp = tid >> 5;
    const int g = lane >> 2, t = lane & 3;
    const int wr = (warp & 1) * 64, wc = (warp >> 1) * 32;
    const int m0 = blockIdx.y * 128, n0 = blockIdx.x * 128;

    float acc[4][4][4];
#pragma unroll
    for (int i = 0; i < 4; i++)
#pragma unroll
        for (int j = 0; j < 4; j++)
#pragma unroll
            for (int q = 0; q < 4; q++) acc[i][j][q] = 0.0f;

    auto ldAB = [&](int s, int kt) {
#pragma unroll
        for (int q = 0; q < 2; q++) {
            int idx = q * 256 + tid;
            int row = idx >> 2, c = idx & 3;
            cp_async16(As + s * 5120 + row * 40 + c * 8,
                       AH + (size_t)(m0 + row) * K + kt * 32 + c * 8);
        }
#pragma unroll
        for (int q = 0; q < 2; q++) {
            int idx = q * 256 + tid;
            int row = idx >> 2, c = idx & 3;
            cp_async16(Bs + s * 5120 + row * 40 + c * 8,
                       BmH + (size_t)(n0 + row) * K + kt * 32 + c * 8);
        }
        asm volatile("cp.async.commit_group;\n" ::);
    };

    ldAB(0, 0);
    asm volatile("cp.async.wait_group 0;\n" ::);
    __syncthreads();

    for (int kt = 0; kt < nk; kt++) {
        int s = kt & 1;
        bool more = (kt + 1 < nk);
        if (more) ldAB(s ^ 1, kt + 1);

        const __half* Asb = As + s * 5120;
        const __half* Bsb = Bs + s * 5120;
#pragma unroll
        for (int kk = 0; kk < 2; kk++) {
            uint32_t af[4][4];
#pragma unroll
            for (int mt = 0; mt < 4; mt++) {
                int row = wr + mt * 16 + g;
                int col = kk * 16 + 2 * t;
                af[mt][0] = *reinterpret_cast<const uint32_t*>(Asb + row * 40 + col);
                af[mt][1] = *reinterpret_cast<const uint32_t*>(Asb + (row + 8) * 40 + col);
                af[mt][2] = *reinterpret_cast<const uint32_t*>(Asb + row * 40 + col + 8);
                af[mt][3] = *reinterpret_cast<const uint32_t*>(Asb + (row + 8) * 40 + col + 8);
            }
            uint32_t bf[4][2];
#pragma unroll
            for (int nt = 0; nt < 4; nt++) {
                int nl = wc + nt * 8 + g;
                int col = kk * 16 + 2 * t;
                bf[nt][0] = *reinterpret_cast<const uint32_t*>(Bsb + nl * 40 + col);
                bf[nt][1] = *reinterpret_cast<const uint32_t*>(Bsb + nl * 40 + col + 8);
            }
#pragma unroll
            for (int mt = 0; mt < 4; mt++)
#pragma unroll
                for (int nt = 0; nt < 4; nt++)
                    mma_f16(acc[mt][nt], af[mt], bf[nt]);
        }
        if (more) asm volatile("cp.async.wait_group 0;\n" ::);
        __syncthreads();
    }

    // epilogue: f -> gmem (fp16) AND stage double-rounded values for local scan
    float* Ys = reinterpret_cast<float*>(smh);   // overlay 128 x 132 fp32
#pragma unroll
    for (int mt = 0; mt < 4; mt++) {
#pragma unroll
        for (int nt = 0; nt < 4; nt++) {
            int rl = wr + mt * 16 + g;
            int ccl = wc + nt * 8 + 2 * t;
            int r0 = m0 + rl;
            __half2 h01 = __floats2half2_rn(acc[mt][nt][0], acc[mt][nt][1]);
            __half2 h23 = __floats2half2_rn(acc[mt][nt][2], acc[mt][nt][3]);
            *reinterpret_cast<__half2*>(F + (size_t)r0 * N + n0 + ccl) = h01;
            *reinterpret_cast<__half2*>(F + (size_t)(r0 + 8) * N + n0 + ccl) = h23;
            float2 v01 = __half22float2(h01);
            float2 v23 = __half22float2(h23);
            *reinterpret_cast<float2*>(Ys + rl * 132 + ccl) = v01;
            *reinterpret_cast<float2*>(Ys + (rl + 8) * 132 + ccl) = v23;
        }
    }
    __syncthreads();

    // local scan: thread -> (col 0..127, chunk 0..1), zero init
    {
        int col = tid & 127, chunk = tid >> 7;
        int ng = n0 + col;
        int p = ng >> 1, c = ng & 1;
        float m11 = g_m11[p], m12 = g_m12[p], m21 = g_dts[p];
        float x1 = 0.0f, x2 = 0.0f;
        const float* base = Ys + (chunk * 64) * 132 + col;
#pragma unroll 8
        for (int j = 0; j < CLEN; j++) {
            float fv = base[j * 132];
            float n1 = fmaf(m11, x1, fmaf(m12, x2, fv));
            float n2 = fmaf(m21, x1, x2);
            x1 = n1; x2 = n2;
        }
        int b = m0 >> 12;
        int ch = ((m0 & 4095) >> 6) + chunk;
        float* cfp = g_cf + ((size_t)(b * 256 + p) * 64 + ch) * 4;
        cfp[c]     = x1;
        cfp[2 + c] = x2;
    }
}

// ---------------------------------------------------------------------------
// Scan phase 2: warp-parallel cross-chunk combine (Kogge-Stone over 32 lanes)
// ---------------------------------------------------------------------------
__global__ void __launch_bounds__(256) scan_combine() {
    const unsigned FULL = 0xFFFFFFFFu;
    int wg = blockIdx.x * 8 + (threadIdx.x >> 5);   // 0..2047
    int lane = threadIdx.x & 31;
    int b = wg >> 8, p = wg & 255;

    float m11 = g_m11[p], m12 = g_m12[p], m21 = g_dts[p];
    float pa = m11, pb = m12, pc = m21, pd = 1.0f;
#pragma unroll
    for (int i = 0; i < 6; i++) {
        float na = fmaf(pa, pa, pb * pc);
        float nb = fmaf(pa, pb, pb * pd);
        float nc = fmaf(pc, pa, pd * pc);
        float nd = fmaf(pc, pb, pd * pd);
        pa = na; pb = nb; pc = nc; pd = nd;
    }

    const float4* cf = reinterpret_cast<const float4*>(g_cf) + (size_t)(b * 256 + p) * 64;
    float4 v0 = cf[2 * lane];
    float4 v1 = cf[2 * lane + 1];

    float w1r = fmaf(pa, v0.x, fmaf(pb, v0.z, v1.x));
    float w1i = fmaf(pa, v0.y, fmaf(pb, v0.w, v1.y));
    float w2r = fmaf(pc, v0.x, fmaf(pd, v0.z, v1.z));
    float w2i = fmaf(pc, v0.y, fmaf(pd, v0.w, v1.w));
    float ma = fmaf(pa, pa, pb * pc), mb = fmaf(pa, pb, pb * pd);
    float mc = fmaf(pc, pa, pd * pc), md = fmaf(pc, pb, pd * pd);

#pragma unroll
    for (int d = 1; d < 32; d <<= 1) {
        float oa = __shfl_up_sync(FULL, ma, d);
        float ob = __shfl_up_sync(FULL, mb, d);
        float oc = __shfl_up_sync(FULL, mc, d);
        float od = __shfl_up_sync(FULL, md, d);
        float o1r = __shfl_up_sync(FULL, w1r, d);
        float o1i = __shfl_up_sync(FULL, w1i, d);
        float o2r = __shfl_up_sync(FULL, w2r, d);
        float o2i = __shfl_up_sync(FULL, w2i, d);
        if (lane >= d) {
            w1r = fmaf(ma, o1r, fmaf(mb, o2r, w1r));
            w1i = fmaf(ma, o1i, fmaf(mb, o2i, w1i));
            w2r = fmaf(mc, o1r, fmaf(md, o2r, w2r));
            w2i = fmaf(mc, o1i, fmaf(md, o2i, w2i));
            float na = fmaf(ma, oa, mb * oc), nb = fmaf(ma, ob, mb * od);
            float nc = fmaf(mc, oa, md * oc), nd = fmaf(mc, ob, md * od);
            ma = na; mb = nb; mc = nc; md = nd;
        }
    }

    float e1r = __shfl_up_sync(FULL, w1r, 1);
    float e1i = __shfl_up_sync(FULL, w1i, 1);
    float e2r = __shfl_up_sync(FULL, w2r, 1);
    float e2i = __shfl_up_sync(FULL, w2i, 1);
    if (lane == 0) { e1r = e1i = e2r = e2i = 0.0f; }

    float4* gi = reinterpret_cast<float4*>(g_init) + (size_t)(b * 256 + p) * 64;
    gi[2 * lane] = make_float4(e1r, e1i, e2r, e2i);
    gi[2 * lane + 1] = make_float4(
        fmaf(pa, e1r, fmaf(pb, e2r, v0.x)),
        fmaf(pa, e1i, fmaf(pb, e2i, v0.y)),
        fmaf(pc, e1r, fmaf(pd, e2r, v0.z)),
        fmaf(pc, e1i, fmaf(pd, e2i, v0.w)));
}

// ---------------------------------------------------------------------------
// Scan phase 3: two chunks per thread (independent chains -> 2x MLP/ILP)
// grid 256: block = (b, chunk-pair); thread = column pair p
// ---------------------------------------------------------------------------
__global__ void scan_final2() {
    int b = blockIdx.x >> 5;
    int cp = blockIdx.x & 31;
    int ch0 = cp * 2;
    int p = threadIdx.x;
    float m11 = g_m11[p], m12 = g_m12[p], m21 = g_dts[p];
    const float4* gi = reinterpret_cast<const float4*>(g_init) + (size_t)(b * 256 + p) * 64;
    float4 ivA = gi[ch0];
    float4 ivB = gi[ch0 + 1];
    float x1rA = ivA.x, x1iA = ivA.y, x2rA = ivA.z, x2iA = ivA.w;
    float x1rB = ivB.x, x1iB = ivB.y, x2rB = ivB.z, x2iB = ivB.w;
    const __half2* fA = reinterpret_cast<const __half2*>(g_fh)
                        + ((size_t)(b * Lc + ch0 * CLEN)) * 256 + p;
    const __half2* fB = fA + (size_t)CLEN * 256;
    __half2* yA = reinterpret_cast<__half2*>(g_ysh)
                  + ((size_t)(b * Lc + ch0 * CLEN)) * 256 + p;
    __half2* yB = yA + (size_t)CLEN * 256;
#pragma unroll 8
    for (int j = 0; j < CLEN; j++) {
        float2 fa = __half22float2(fA[(size_t)j * 256]);
        float2 fb = __half22float2(fB[(size_t)j * 256]);
        float n1rA = fmaf(m11, x1rA, fmaf(m12, x2rA, fa.x));
        float n2rA = fmaf(m21, x1rA, x2rA);
        float n1iA = fmaf(m11, x1iA, fmaf(m12, x2iA, fa.y));
        float n2iA = fmaf(m21, x1iA, x2iA);
        float n1rB = fmaf(m11, x1rB, fmaf(m12, x2rB, fb.x));
        float n2rB = fmaf(m21, x1rB, x2rB);
        float n1iB = fmaf(m11, x1iB, fmaf(m12, x2iB, fb.y));
        float n2iB = fmaf(m21, x1iB, x2iB);
        x1rA = n1rA; x2rA = n2rA; x1iA = n1iA; x2iA = n2iA;
        x1rB = n1rB; x2rB = n2rB; x1iB = n1iB; x2iB = n2iB;
        yA[(size_t)j * 256] = __floats2half2_rn(x2rA, x2iA);
        yB[(size_t)j * 256] = __floats2half2_rn(x2rB, x2iB);
    }
}

// ---------------------------------------------------------------------------
// GEMM2: out = ys @ Cop^T + D*u  (M=32768, N=256, K=512); u fp16 in epilogue
// ---------------------------------------------------------------------------
__global__ void __launch_bounds__(256, 2)
gemm2_f16(const __half* __restrict__ AH, const __half* __restrict__ BmH,
          float* __restrict__ Out, const __half* __restrict__ UH,
          const float* __restrict__ Dv) {
    constexpr int N = 256, K = 512, nk = K / 32;
    extern __shared__ __half smh[];
    __half* As = smh;                 // 2 stages * 128*40
    __half* Bs = smh + 2 * 5120;

    const int tid  = threadIdx.x;
    const int lane = tid & 31, warp = tid >> 5;
    const int g = lane >> 2, t = lane & 3;
    const int wr = (warp & 1) * 64, wc = (warp >> 1) * 32;
    const int m0 = blockIdx.y * 128, n0 = blockIdx.x * 128;

    float acc[4][4][4];
#pragma unroll
    for (int i = 0; i < 4; i++)
#pragma unroll
        for (int j = 0; j < 4; j++)
#pragma unroll
            for (int q = 0; q < 4; q++) acc[i][j][q] = 0.0f;

    auto ldAB = [&](int s, int kt) {
#pragma unroll
        for (int q = 0; q < 2; q++) {
            int idx = q * 256 + tid;
            int row = idx >> 2, c = idx & 3;
            cp_async16(As + s * 5120 + row * 40 + c * 8,
                       AH + (size_t)(m0 + row) * K + kt * 32 + c * 8);
        }
#pragma unroll
        for (int q = 0; q < 2; q++) {
            int idx = q * 256 + tid;
            int row = idx >> 2, c = idx & 3;
            cp_async16(Bs + s * 5120 + row * 40 + c * 8,
                       BmH + (size_t)(n0 + row) * K + kt * 32 + c * 8);
        }
        asm volatile("cp.async.commit_group;\n" ::);
    };

    ldAB(0, 0);
    asm volatile("cp.async.wait_group 0;\n" ::);
    __syncthreads();

    for (int kt = 0; kt < nk; kt++) {
        int s = kt & 1;
        bool more = (kt + 1 < nk);
        if (more) ldAB(s ^ 1, kt + 1);

        const __half* Asb = As + s * 5120;
        const __half* Bsb = Bs + s * 5120;
#pragma unroll
        for (int kk = 0; kk < 2; kk++) {
            uint32_t af[4][4];
#pragma unroll
            for (int mt = 0; mt < 4; mt++) {
                int row = wr + mt * 16 + g;
                int col = kk * 16 + 2 * t;
                af[mt][0] = *reinterpret_cast<const uint32_t*>(Asb + row * 40 + col);
                af[mt][1] = *reinterpret_cast<const uint32_t*>(Asb + (row + 8) * 40 + col);
                af[mt][2] = *reinterpret_cast<const uint32_t*>(Asb + row * 40 + col + 8);
                af[mt][3] = *reinterpret_cast<const uint32_t*>(Asb + (row + 8) * 40 + col + 8);
            }
            uint32_t bf[4][2];
#pragma unroll
            for (int nt = 0; nt < 4; nt++) {
                int nl = wc + nt * 8 + g;
                int col = kk * 16 + 2 * t;
                bf[nt][0] = *reinterpret_cast<const uint32_t*>(Bsb + nl * 40 + col);
                bf[nt][1] = *reinterpret_cast<const uint32_t*>(Bsb + nl * 40 + col + 8);
            }
#pragma unroll
            for (int mt = 0; mt < 4; mt++)
#pragma unroll
                for (int nt = 0; nt < 4; nt++)
                    mma_f16(acc[mt][nt], af[mt], bf[nt]);
        }
        if (more) asm volatile("cp.async.wait_group 0;\n" ::);
        __syncthreads();
    }

    // epilogue: + D*u (u fp16), write out
#pragma unroll
    for (int mt = 0; mt < 4; mt++) {
#pragma unroll
        for (int nt = 0; nt < 4; nt++) {
            int r0 = m0 + wr + mt * 16 + g;
            int cc = n0 + wc + nt * 8 + 2 * t;
            float d0 = Dv[cc], d1 = Dv[cc + 1];
            float2 u0 = __half22float2(
                *reinterpret_cast<const __half2*>(UH + (size_t)r0 * 256 + cc));
            float2 u1 = __half22float2(
                *reinterpret_cast<const __half2*>(UH + (size_t)(r0 + 8) * 256 + cc));
            float v0 = fmaf(d0, u0.x, acc[mt][nt][0]);
            float v1 = fmaf(d1, u0.y, acc[mt][nt][1]);
            float v2 = fmaf(d0, u1.x, acc[mt][nt][2]);
            float v3 = fmaf(d1, u1.y, acc[mt][nt][3]);
            *reinterpret_cast<float2*>(Out + (size_t)r0 * N + cc) = make_float2(v0, v1);
            *reinterpret_cast<float2*>(Out + (size_t)(r0 + 8) * N + cc) = make_float2(v2, v3);
        }
    }
}

// ---------------------------------------------------------------------------
extern "C" void kernel_launch(void* const* d_in, const int* in_sizes, int n_in,
                              void* d_out, int out_size) {
    const float* u  = (const float*)d_in[0];
    const float* Ad = (const float*)d_in[1];
    const float* Gd = (const float*)d_in[2];
    const float* dt = (const float*)d_in[3];
    const float* Bm = (const float*)d_in[4];
    const float* Cm = (const float*)d_in[5];
    const float* Dv = (const float*)d_in[6];
    float* out = (float*)d_out;

    __half *uh, *fptr, *ysptr, *bop, *cop;
    cudaGetSymbolAddress((void**)&uh,    g_uh);
    cudaGetSymbolAddress((void**)&fptr,  g_fh);
    cudaGetSymbolAddress((void**)&ysptr, g_ysh);
    cudaGetSymbolAddress((void**)&bop,   g_BopH);
    cudaGetSymbolAddress((void**)&cop,   g_CopH);

    const int smem1 = 128 * 132 * 4;        // 67584 (fp32 scan overlay dominates)
    const int smem2 = 4 * 5120 * 2;         // 40960
    cudaFuncSetAttribute(gemm1_f16,
                         cudaFuncAttributeMaxDynamicSharedMemorySize, smem1);
    cudaFuncSetAttribute(gemm2_f16,
                         cudaFuncAttributeMaxDynamicSharedMemorySize, smem2);

    u2h_kernel<<<Mrows * 256 / (256 * 8), 256>>>(u);
    prep_kernel<<<256, 512>>>(Ad, Gd, dt, Bm, Cm);

    // GEMM1 + fused local scan: f = u @ Bop^T (fp16 out), chunk states -> g_cf
    gemm1_f16<<<dim3(4, 256), 256, smem1>>>(uh, bop, fptr);

    scan_combine<<<256, 256>>>();

    // final scan: ys = scan(f), fp16 in/out, 2 chunks per thread
    scan_final2<<<Bc * NCHUNK / 2, 256>>>();

    // GEMM2: out = ys @ Cop^T + D*u (u fp16)
    gemm2_f16<<<dim3(2, 256), 256, smem2>>>(ysptr, cop, out, uh, Dv);
}

// round 15
// speedup vs baseline: 1.0149x; 1.0149x over previous
#include <cuda_runtime.h>
#include <cuda_fp16.h>
#include <cstdint>

// Problem constants
constexpr int Bc = 8, Lc = 4096;
constexpr int Mrows = Bc * Lc;          // 32768
constexpr int NCHUNK = 64, CLEN = 64;   // 64 chunks of 64 steps

// Scratch (static device arrays -- no allocation allowed)
__device__ __half g_uh [(size_t)Mrows * 256]; // u  (fp16): [bl][h]
__device__ __half g_fh [(size_t)Mrows * 512]; // f  (fp16): [bl][2p+c]
__device__ __half g_ysh[(size_t)Mrows * 512]; // ys (fp16), same layout
__device__ __half g_BopH[512 * 256];          // GEMM1 B, [n=2p+c][k=h]
__device__ __half g_CopH[256 * 512];          // GEMM2 B, [n=h][k=2p+c]
__device__ float  g_m11[256], g_m12[256], g_dts[256];
__device__ float  g_cf  [Bc * 256 * NCHUNK * 4]; // [b][p][ch] float4
__device__ float  g_init[Bc * 256 * NCHUNK * 4];

constexpr int STG = 5120;   // halves per operand stage (128 rows x 40)

__device__ __forceinline__ void cp_async16(void* smem, const void* gmem) {
    uint32_t s = (uint32_t)__cvta_generic_to_shared(smem);
    asm volatile("cp.async.ca.shared.global [%0], [%1], 16;\n" :: "r"(s), "l"(gmem));
}

__device__ __forceinline__ void mma_f16(float c[4], const uint32_t a[4], const uint32_t b[2]) {
    asm volatile(
        "mma.sync.aligned.m16n8k16.row.col.f32.f16.f16.f32 "
        "{%0,%1,%2,%3}, {%4,%5,%6,%7}, {%8,%9}, {%0,%1,%2,%3};\n"
        : "+f"(c[0]), "+f"(c[1]), "+f"(c[2]), "+f"(c[3])
        : "r"(a[0]), "r"(a[1]), "r"(a[2]), "r"(a[3]), "r"(b[0]), "r"(b[1]));
}

// ---------------------------------------------------------------------------
// u -> fp16 pre-pass: 8M floats, 8 per thread
// ---------------------------------------------------------------------------
__global__ void u2h_kernel(const float* __restrict__ U) {
    size_t i = ((size_t)blockIdx.x * 256 + threadIdx.x) * 8;
    float4 a = *reinterpret_cast<const float4*>(U + i);
    float4 b = *reinterpret_cast<const float4*>(U + i + 4);
    __half2 h0 = __floats2half2_rn(a.x, a.y);
    __half2 h1 = __floats2half2_rn(a.z, a.w);
    __half2 h2 = __floats2half2_rn(b.x, b.y);
    __half2 h3 = __floats2half2_rn(b.z, b.w);
    uint4 pk;
    pk.x = *reinterpret_cast<uint32_t*>(&h0);
    pk.y = *reinterpret_cast<uint32_t*>(&h1);
    pk.z = *reinterpret_cast<uint32_t*>(&h2);
    pk.w = *reinterpret_cast<uint32_t*>(&h3);
    *reinterpret_cast<uint4*>(g_uh + i) = pk;
}

// ---------------------------------------------------------------------------
// Prep: per-p recurrence params + fp16 operand matrices (B stored [n][k])
// ---------------------------------------------------------------------------
__global__ void prep_kernel(const float* __restrict__ Ad, const float* __restrict__ Gd,
                            const float* __restrict__ dt, const float* __restrict__ Bm,
                            const float* __restrict__ Cm) {
    int h = blockIdx.x;          // 0..255
    int n = threadIdx.x;         // 0..511
    int p = n >> 1;
    int c = n & 1;
    float dts = 1.0f / (1.0f + expf(-dt[p]));
    float G = fmaxf(Gd[p], dts * Ad[p]);
    float A = fmaxf(Ad[p], 0.25f * G * G);

    g_BopH[n * 256 + h] = __float2half(dts * Bm[p * 512 + h * 2 + c]);
    float cv = Cm[h * 512 + p * 2 + c];
    g_CopH[h * 512 + n] = __float2half(c ? -cv : cv);

    if (h == 0 && c == 0) {
        g_m11[p] = 1.0f - dts * G;
        g_m12[p] = -dts * A;
        g_dts[p] = dts;          // m21; m22 == 1
    }
}

// ---------------------------------------------------------------------------
// GEMM1 (+ fused local scan): f = u @ Bop^T  (M=32768, N=512, K=256)
// 4-stage cp.async pipeline; epilogue: f fp16 + local scans -> g_cf.
// ---------------------------------------------------------------------------
__global__ void __launch_bounds__(256, 2)
gemm1_f16(const __half* __restrict__ AH, const __half* __restrict__ BmH,
          __half* __restrict__ F) {
    constexpr int N = 512, K = 256, nk = K / 32;
    extern __shared__ __half smh[];
    __half* As = smh;                 // 4 stages * STG
    __half* Bs = smh + 4 * STG;

    const int tid  = threadIdx.x;
    const int lane = tid & 31, warp = tid >> 5;
    const int g = lane >> 2, t = lane & 3;
    const int wr = (warp & 1) * 64, wc = (warp >> 1) * 32;
    const int m0 = blockIdx.y * 128, n0 = blockIdx.x * 128;

    float acc[4][4][4];
#pragma unroll
    for (int i = 0; i < 4; i++)
#pragma unroll
        for (int j = 0; j < 4; j++)
#pragma unroll
            for (int q = 0; q < 4; q++) acc[i][j][q] = 0.0f;

    auto ldAB = [&](int s, int kt) {
#pragma unroll
        for (int q = 0; q < 2; q++) {
            int idx = q * 256 + tid;
            int row = idx >> 2, c = idx & 3;
            cp_async16(As + s * STG + row * 40 + c * 8,
                       AH + (size_t)(m0 + row) * K + kt * 32 + c * 8);
        }
#pragma unroll
        for (int q = 0; q < 2; q++) {
            int idx = q * 256 + tid;
            int row = idx >> 2, c = idx & 3;
            cp_async16(Bs + s * STG + row * 40 + c * 8,
                       BmH + (size_t)(n0 + row) * K + kt * 32 + c * 8);
        }
        asm volatile("cp.async.commit_group;\n" ::);
    };

    // prologue: stages 0..2
    ldAB(0, 0); ldAB(1, 1); ldAB(2, 2);

    for (int kt = 0; kt < nk; kt++) {
        if (kt <= nk - 3)      asm volatile("cp.async.wait_group 2;\n" ::);
        else if (kt == nk - 2) asm volatile("cp.async.wait_group 1;\n" ::);
        else                   asm volatile("cp.async.wait_group 0;\n" ::);
        __syncthreads();
        if (kt + 3 < nk) ldAB((kt + 3) & 3, kt + 3);

        int s = kt & 3;
        const __half* Asb = As + s * STG;
        const __half* Bsb = Bs + s * STG;
#pragma unroll
        for (int kk = 0; kk < 2; kk++) {
            uint32_t af[4][4];
#pragma unroll
            for (int mt = 0; mt < 4; mt++) {
                int row = wr + mt * 16 + g;
                int col = kk * 16 + 2 * t;
                af[mt][0] = *reinterpret_cast<const uint32_t*>(Asb + row * 40 + col);
                af[mt][1] = *reinterpret_cast<const uint32_t*>(Asb + (row + 8) * 40 + col);
                af[mt][2] = *reinterpret_cast<const uint32_t*>(Asb + row * 40 + col + 8);
                af[mt][3] = *reinterpret_cast<const uint32_t*>(Asb + (row + 8) * 40 + col + 8);
            }
            uint32_t bf[4][2];
#pragma unroll
            for (int nt = 0; nt < 4; nt++) {
                int nl = wc + nt * 8 + g;
                int col = kk * 16 + 2 * t;
                bf[nt][0] = *reinterpret_cast<const uint32_t*>(Bsb + nl * 40 + col);
                bf[nt][1] = *reinterpret_cast<const uint32_t*>(Bsb + nl * 40 + col + 8);
            }
#pragma unroll
            for (int mt = 0; mt < 4; mt++)
#pragma unroll
                for (int nt = 0; nt < 4; nt++)
                    mma_f16(acc[mt][nt], af[mt], bf[nt]);
        }
    }
    __syncthreads();   // all MMA smem reads done before Ys overlay

    // epilogue: f -> gmem (fp16) AND stage double-rounded values for local scan
    float* Ys = reinterpret_cast<float*>(smh);   // overlay 128 x 132 fp32
#pragma unroll
    for (int mt = 0; mt < 4; mt++) {
#pragma unroll
        for (int nt = 0; nt < 4; nt++) {
            int rl = wr + mt * 16 + g;
            int ccl = wc + nt * 8 + 2 * t;
            int r0 = m0 + rl;
            __half2 h01 = __floats2half2_rn(acc[mt][nt][0], acc[mt][nt][1]);
            __half2 h23 = __floats2half2_rn(acc[mt][nt][2], acc[mt][nt][3]);
            *reinterpret_cast<__half2*>(F + (size_t)r0 * N + n0 + ccl) = h01;
            *reinterpret_cast<__half2*>(F + (size_t)(r0 + 8) * N + n0 + ccl) = h23;
            float2 v01 = __half22float2(h01);
            float2 v23 = __half22float2(h23);
            *reinterpret_cast<float2*>(Ys + rl * 132 + ccl) = v01;
            *reinterpret_cast<float2*>(Ys + (rl + 8) * 132 + ccl) = v23;
        }
    }
    __syncthreads();

    // local scan: thread -> (col 0..127, chunk 0..1), zero init
    {
        int col = tid & 127, chunk = tid >> 7;
        int ng = n0 + col;
        int p = ng >> 1, c = ng & 1;
        float m11 = g_m11[p], m12 = g_m12[p], m21 = g_dts[p];
        float x1 = 0.0f, x2 = 0.0f;
        const float* base = Ys + (chunk * 64) * 132 + col;
#pragma unroll 8
        for (int j = 0; j < CLEN; j++) {
            float fv = base[j * 132];
            float n1 = fmaf(m11, x1, fmaf(m12, x2, fv));
            float n2 = fmaf(m21, x1, x2);
            x1 = n1; x2 = n2;
        }
        int b = m0 >> 12;
        int ch = ((m0 & 4095) >> 6) + chunk;
        float* cfp = g_cf + ((size_t)(b * 256 + p) * 64 + ch) * 4;
        cfp[c]     = x1;
        cfp[2 + c] = x2;
    }
}

// ---------------------------------------------------------------------------
// Scan phase 2: warp-parallel cross-chunk combine (Kogge-Stone over 32 lanes)
// ---------------------------------------------------------------------------
__global__ void __launch_bounds__(256) scan_combine() {
    const unsigned FULL = 0xFFFFFFFFu;
    int wg = blockIdx.x * 8 + (threadIdx.x >> 5);   // 0..2047
    int lane = threadIdx.x & 31;
    int b = wg >> 8, p = wg & 255;

    float m11 = g_m11[p], m12 = g_m12[p], m21 = g_dts[p];
    float pa = m11, pb = m12, pc = m21, pd = 1.0f;
#pragma unroll
    for (int i = 0; i < 6; i++) {
        float na = fmaf(pa, pa, pb * pc);
        float nb = fmaf(pa, pb, pb * pd);
        float nc = fmaf(pc, pa, pd * pc);
        float nd = fmaf(pc, pb, pd * pd);
        pa = na; pb = nb; pc = nc; pd = nd;
    }

    const float4* cf = reinterpret_cast<const float4*>(g_cf) + (size_t)(b * 256 + p) * 64;
    float4 v0 = cf[2 * lane];
    float4 v1 = cf[2 * lane + 1];

    float w1r = fmaf(pa, v0.x, fmaf(pb, v0.z, v1.x));
    float w1i = fmaf(pa, v0.y, fmaf(pb, v0.w, v1.y));
    float w2r = fmaf(pc, v0.x, fmaf(pd, v0.z, v1.z));
    float w2i = fmaf(pc, v0.y, fmaf(pd, v0.w, v1.w));
    float ma = fmaf(pa, pa, pb * pc), mb = fmaf(pa, pb, pb * pd);
    float mc = fmaf(pc, pa, pd * pc), md = fmaf(pc, pb, pd * pd);

#pragma unroll
    for (int d = 1; d < 32; d <<= 1) {
        float oa = __shfl_up_sync(FULL, ma, d);
        float ob = __shfl_up_sync(FULL, mb, d);
        float oc = __shfl_up_sync(FULL, mc, d);
        float od = __shfl_up_sync(FULL, md, d);
        float o1r = __shfl_up_sync(FULL, w1r, d);
        float o1i = __shfl_up_sync(FULL, w1i, d);
        float o2r = __shfl_up_sync(FULL, w2r, d);
        float o2i = __shfl_up_sync(FULL, w2i, d);
        if (lane >= d) {
            w1r = fmaf(ma, o1r, fmaf(mb, o2r, w1r));
            w1i = fmaf(ma, o1i, fmaf(mb, o2i, w1i));
            w2r = fmaf(mc, o1r, fmaf(md, o2r, w2r));
            w2i = fmaf(mc, o1i, fmaf(md, o2i, w2i));
            float na = fmaf(ma, oa, mb * oc), nb = fmaf(ma, ob, mb * od);
            float nc = fmaf(mc, oa, md * oc), nd = fmaf(mc, ob, md * od);
            ma = na; mb = nb; mc = nc; md = nd;
        }
    }

    float e1r = __shfl_up_sync(FULL, w1r, 1);
    float e1i = __shfl_up_sync(FULL, w1i, 1);
    float e2r = __shfl_up_sync(FULL, w2r, 1);
    float e2i = __shfl_up_sync(FULL, w2i, 1);
    if (lane == 0) { e1r = e1i = e2r = e2i = 0.0f; }

    float4* gi = reinterpret_cast<float4*>(g_init) + (size_t)(b * 256 + p) * 64;
    gi[2 * lane] = make_float4(e1r, e1i, e2r, e2i);
    gi[2 * lane + 1] = make_float4(
        fmaf(pa, e1r, fmaf(pb, e2r, v0.x)),
        fmaf(pa, e1i, fmaf(pb, e2i, v0.y)),
        fmaf(pc, e1r, fmaf(pd, e2r, v0.z)),
        fmaf(pc, e1i, fmaf(pd, e2i, v0.w)));
}

// ---------------------------------------------------------------------------
// Scan phase 3: two chunks per thread (independent chains -> 2x MLP/ILP)
// ---------------------------------------------------------------------------
__global__ void scan_final2() {
    int b = blockIdx.x >> 5;
    int cp = blockIdx.x & 31;
    int ch0 = cp * 2;
    int p = threadIdx.x;
    float m11 = g_m11[p], m12 = g_m12[p], m21 = g_dts[p];
    const float4* gi = reinterpret_cast<const float4*>(g_init) + (size_t)(b * 256 + p) * 64;
    float4 ivA = gi[ch0];
    float4 ivB = gi[ch0 + 1];
    float x1rA = ivA.x, x1iA = ivA.y, x2rA = ivA.z, x2iA = ivA.w;
    float x1rB = ivB.x, x1iB = ivB.y, x2rB = ivB.z, x2iB = ivB.w;
    const __half2* fA = reinterpret_cast<const __half2*>(g_fh)
                        + ((size_t)(b * Lc + ch0 * CLEN)) * 256 + p;
    const __half2* fB = fA + (size_t)CLEN * 256;
    __half2* yA = reinterpret_cast<__half2*>(g_ysh)
                  + ((size_t)(b * Lc + ch0 * CLEN)) * 256 + p;
    __half2* yB = yA + (size_t)CLEN * 256;
#pragma unroll 8
    for (int j = 0; j < CLEN; j++) {
        float2 fa = __half22float2(fA[(size_t)j * 256]);
        float2 fb = __half22float2(fB[(size_t)j * 256]);
        float n1rA = fmaf(m11, x1rA, fmaf(m12, x2rA, fa.x));
        float n2rA = fmaf(m21, x1rA, x2rA);
        float n1iA = fmaf(m11, x1iA, fmaf(m12, x2iA, fa.y));
        float n2iA = fmaf(m21, x1iA, x2iA);
        float n1rB = fmaf(m11, x1rB, fmaf(m12, x2rB, fb.x));
        float n2rB = fmaf(m21, x1rB, x2rB);
        float n1iB = fmaf(m11, x1iB, fmaf(m12, x2iB, fb.y));
        float n2iB = fmaf(m21, x1iB, x2iB);
        x1rA = n1rA; x2rA = n2rA; x1iA = n1iA; x2iA = n2iA;
        x1rB = n1rB; x2rB = n2rB; x1iB = n1iB; x2iB = n2iB;
        yA[(size_t)j * 256] = __floats2half2_rn(x2rA, x2iA);
        yB[(size_t)j * 256] = __floats2half2_rn(x2rB, x2iB);
    }
}

// ---------------------------------------------------------------------------
// GEMM2: out = ys @ Cop^T + D*u  (M=32768, N=256, K=512); 4-stage pipeline
// ---------------------------------------------------------------------------
__global__ void __launch_bounds__(256, 2)
gemm2_f16(const __half* __restrict__ AH, const __half* __restrict__ BmH,
          float* __restrict__ Out, const __half* __restrict__ UH,
          const float* __restrict__ Dv) {
    constexpr int N = 256, K = 512, nk = K / 32;
    extern __shared__ __half smh[];
    __half* As = smh;                 // 4 stages * STG
    __half* Bs = smh + 4 * STG;

    const int tid  = threadIdx.x;
    const int lane = tid & 31, warp = tid >> 5;
    const int g = lane >> 2, t = lane & 3;
    const int wr = (warp & 1) * 64, wc = (warp >> 1) * 32;
    const int m0 = blockIdx.y * 128, n0 = blockIdx.x * 128;

    float acc[4][4][4];
#pragma unroll
    for (int i = 0; i < 4; i++)
#pragma unroll
        for (int j = 0; j < 4; j++)
#pragma unroll
            for (int q = 0; q < 4; q++) acc[i][j][q] = 0.0f;

    auto ldAB = [&](int s, int kt) {
#pragma unroll
        for (int q = 0; q < 2; q++) {
            int idx = q * 256 + tid;
            int row = idx >> 2, c = idx & 3;
            cp_async16(As + s * STG + row * 40 + c * 8,
                       AH + (size_t)(m0 + row) * K + kt * 32 + c * 8);
        }
#pragma unroll
        for (int q = 0; q < 2; q++) {
            int idx = q * 256 + tid;
            int row = idx >> 2, c = idx & 3;
            cp_async16(Bs + s * STG + row * 40 + c * 8,
                       BmH + (size_t)(n0 + row) * K + kt * 32 + c * 8);
        }
        asm volatile("cp.async.commit_group;\n" ::);
    };

    ldAB(0, 0); ldAB(1, 1); ldAB(2, 2);

    for (int kt = 0; kt < nk; kt++) {
        if (kt <= nk - 3)      asm volatile("cp.async.wait_group 2;\n" ::);
        else if (kt == nk - 2) asm volatile("cp.async.wait_group 1;\n" ::);
        else                   asm volatile("cp.async.wait_group 0;\n" ::);
        __syncthreads();
        if (kt + 3 < nk) ldAB((kt + 3) & 3, kt + 3);

        int s = kt & 3;
        const __half* Asb = As + s * STG;
        const __half* Bsb = Bs + s * STG;
#pragma unroll
        for (int kk = 0; kk < 2; kk++) {
            uint32_t af[4][4];
#pragma unroll
            for (int mt = 0; mt < 4; mt++) {
                int row = wr + mt * 16 + g;
                int col = kk * 16 + 2 * t;
                af[mt][0] = *reinterpret_cast<const uint32_t*>(Asb + row * 40 + col);
                af[mt][1] = *reinterpret_cast<const uint32_t*>(Asb + (row + 8) * 40 + col);
                af[mt][2] = *reinterpret_cast<const uint32_t*>(Asb + row * 40 + col + 8);
                af[mt][3] = *reinterpret_cast<const uint32_t*>(Asb + (row + 8) * 40 + col + 8);
            }
            uint32_t bf[4][2];
#pragma unroll
            for (int nt = 0; nt < 4; nt++) {
                int nl = wc + nt * 8 + g;
                int col = kk * 16 + 2 * t;
                bf[nt][0] = *reinterpret_cast<const uint32_t*>(Bsb + nl * 40 + col);
                bf[nt][1] = *reinterpret_cast<const uint32_t*>(Bsb + nl * 40 + col + 8);
            }
#pragma unroll
            for (int mt = 0; mt < 4; mt++)
#pragma unroll
                for (int nt = 0; nt < 4; nt++)
                    mma_f16(acc[mt][nt], af[mt], bf[nt]);
        }
    }

    // epilogue: + D*u (u fp16), write out
#pragma unroll
    for (int mt = 0; mt < 4; mt++) {
#pragma unroll
        for (int nt = 0; nt < 4; nt++) {
            int r0 = m0 + wr + mt * 16 + g;
            int cc = n0 + wc + nt * 8 + 2 * t;
            float d0 = Dv[cc], d1 = Dv[cc + 1];
            float2 u0 = __half22float2(
                *reinterpret_cast<const __half2*>(UH + (size_t)r0 * 256 + cc));
            float2 u1 = __half22float2(
                *reinterpret_cast<const __half2*>(UH + (size_t)(r0 + 8) * 256 + cc));
            float v0 = fmaf(d0, u0.x, acc[mt][nt][0]);
            float v1 = fmaf(d1, u0.y, acc[mt][nt][1]);
            float v2 = fmaf(d0, u1.x, acc[mt][nt][2]);
            float v3 = fmaf(d1, u1.y, acc[mt][nt][3]);
            *reinterpret_cast<float2*>(Out + (size_t)r0 * N + cc) = make_float2(v0, v1);
            *reinterpret_cast<float2*>(Out + (size_t)(r0 + 8) * N + cc) = make_float2(v2, v3);
        }
    }
}

// ---------------------------------------------------------------------------
extern "C" void kernel_launch(void* const* d_in, const int* in_sizes, int n_in,
                              void* d_out, int out_size) {
    const float* u  = (const float*)d_in[0];
    const float* Ad = (const float*)d_in[1];
    const float* Gd = (const float*)d_in[2];
    const float* dt = (const float*)d_in[3];
    const float* Bm = (const float*)d_in[4];
    const float* Cm = (const float*)d_in[5];
    const float* Dv = (const float*)d_in[6];
    float* out = (float*)d_out;

    __half *uh, *fptr, *ysptr, *bop, *cop;
    cudaGetSymbolAddress((void**)&uh,    g_uh);
    cudaGetSymbolAddress((void**)&fptr,  g_fh);
    cudaGetSymbolAddress((void**)&ysptr, g_ysh);
    cudaGetSymbolAddress((void**)&bop,   g_BopH);
    cudaGetSymbolAddress((void**)&cop,   g_CopH);

    const int smem_pipe = 8 * STG * 2;              // 81920 (4 stages A+B)
    const int smem1 = smem_pipe;                    // > 67584 Ys overlay
    const int smem2 = smem_pipe;
    cudaFuncSetAttribute(gemm1_f16,
                         cudaFuncAttributeMaxDynamicSharedMemorySize, smem1);
    cudaFuncSetAttribute(gemm2_f16,
                         cudaFuncAttributeMaxDynamicSharedMemorySize, smem2);

    u2h_kernel<<<Mrows * 256 / (256 * 8), 256>>>(u);
    prep_kernel<<<256, 512>>>(Ad, Gd, dt, Bm, Cm);

    // GEMM1 + fused local scan: f = u @ Bop^T (fp16 out), chunk states -> g_cf
    gemm1_f16<<<dim3(4, 256), 256, smem1>>>(uh, bop, fptr);

    scan_combine<<<256, 256>>>();

    // final scan: ys = scan(f), fp16 in/out, 2 chunks per thread
    scan_final2<<<Bc * NCHUNK / 2, 256>>>();

    // GEMM2: out = ys @ Cop^T + D*u (u fp16)
    gemm2_f16<<<dim3(2, 256), 256, smem2>>>(ysptr, cop, out, uh, Dv);
}

// round 16
// speedup vs baseline: 1.0932x; 1.0771x over previous
#include <cuda_runtime.h>
#include <cuda_fp16.h>
#include <cstdint>

// Problem constants
constexpr int Bc = 8, Lc = 4096;
constexpr int Mrows = Bc * Lc;          // 32768
constexpr int NCHUNK = 64, CLEN = 64;   // 64 chunks of 64 steps

// Scratch (static device arrays -- no allocation allowed)
__device__ __half g_uh [(size_t)Mrows * 256]; // u  (fp16): [bl][h]
__device__ __half g_fh [(size_t)Mrows * 512]; // f  (fp16): [bl][2p+c]
__device__ __half g_ysh[(size_t)Mrows * 512]; // ys (fp16), same layout
__device__ __half g_BopH[512 * 256];          // GEMM1 B, [n=2p+c][k=h]
__device__ __half g_CopH[256 * 512];          // GEMM2 B, [n=h][k=2p+c]
__device__ float  g_m11[256], g_m12[256], g_dts[256];
__device__ float  g_cf  [Bc * 256 * NCHUNK * 4]; // [b][p][ch] float4
__device__ float  g_init[Bc * 256 * NCHUNK * 4];

constexpr int STG = 9216;   // halves per operand stage (128 rows x 72, k-tile 64)

__device__ __forceinline__ void cp_async16(void* smem, const void* gmem) {
    uint32_t s = (uint32_t)__cvta_generic_to_shared(smem);
    asm volatile("cp.async.ca.shared.global [%0], [%1], 16;\n" :: "r"(s), "l"(gmem));
}

__device__ __forceinline__ void mma_f16(float c[4], const uint32_t a[4], const uint32_t b[2]) {
    asm volatile(
        "mma.sync.aligned.m16n8k16.row.col.f32.f16.f16.f32 "
        "{%0,%1,%2,%3}, {%4,%5,%6,%7}, {%8,%9}, {%0,%1,%2,%3};\n"
        : "+f"(c[0]), "+f"(c[1]), "+f"(c[2]), "+f"(c[3])
        : "r"(a[0]), "r"(a[1]), "r"(a[2]), "r"(a[3]), "r"(b[0]), "r"(b[1]));
}

// ---------------------------------------------------------------------------
// u -> fp16 pre-pass: 8M floats, 8 per thread
// ---------------------------------------------------------------------------
__global__ void u2h_kernel(const float* __restrict__ U) {
    size_t i = ((size_t)blockIdx.x * 256 + threadIdx.x) * 8;
    float4 a = *reinterpret_cast<const float4*>(U + i);
    float4 b = *reinterpret_cast<const float4*>(U + i + 4);
    __half2 h0 = __floats2half2_rn(a.x, a.y);
    __half2 h1 = __floats2half2_rn(a.z, a.w);
    __half2 h2 = __floats2half2_rn(b.x, b.y);
    __half2 h3 = __floats2half2_rn(b.z, b.w);
    uint4 pk;
    pk.x = *reinterpret_cast<uint32_t*>(&h0);
    pk.y = *reinterpret_cast<uint32_t*>(&h1);
    pk.z = *reinterpret_cast<uint32_t*>(&h2);
    pk.w = *reinterpret_cast<uint32_t*>(&h3);
    *reinterpret_cast<uint4*>(g_uh + i) = pk;
}

// ---------------------------------------------------------------------------
// Prep: per-p recurrence params + fp16 operand matrices (B stored [n][k])
// ---------------------------------------------------------------------------
__global__ void prep_kernel(const float* __restrict__ Ad, const float* __restrict__ Gd,
                            const float* __restrict__ dt, const float* __restrict__ Bm,
                            const float* __restrict__ Cm) {
    int h = blockIdx.x;          // 0..255
    int n = threadIdx.x;         // 0..511
    int p = n >> 1;
    int c = n & 1;
    float dts = 1.0f / (1.0f + expf(-dt[p]));
    float G = fmaxf(Gd[p], dts * Ad[p]);
    float A = fmaxf(Ad[p], 0.25f * G * G);

    g_BopH[n * 256 + h] = __float2half(dts * Bm[p * 512 + h * 2 + c]);
    float cv = Cm[h * 512 + p * 2 + c];
    g_CopH[h * 512 + n] = __float2half(c ? -cv : cv);

    if (h == 0 && c == 0) {
        g_m11[p] = 1.0f - dts * G;
        g_m12[p] = -dts * A;
        g_dts[p] = dts;          // m21; m22 == 1
    }
}

// ---------------------------------------------------------------------------
// GEMM1 (+ fused local scan): f = u @ Bop^T  (M=32768, N=512, K=256)
// k-tile 64, 2-stage cp.async. Epilogue: f fp16 + local scans -> g_cf.
// ---------------------------------------------------------------------------
__global__ void __launch_bounds__(256, 2)
gemm1_f16(const __half* __restrict__ AH, const __half* __restrict__ BmH,
          __half* __restrict__ F) {
    constexpr int N = 512, K = 256, nk = K / 64;
    extern __shared__ __half smh[];
    __half* As = smh;                 // 2 stages * STG
    __half* Bs = smh + 2 * STG;

    const int tid  = threadIdx.x;
    const int lane = tid & 31, warp = tid >> 5;
    const int g = lane >> 2, t = lane & 3;
    const int wr = (warp & 1) * 64, wc = (warp >> 1) * 32;
    const int m0 = blockIdx.y * 128, n0 = blockIdx.x * 128;

    float acc[4][4][4];
#pragma unroll
    for (int i = 0; i < 4; i++)
#pragma unroll
        for (int j = 0; j < 4; j++)
#pragma unroll
            for (int q = 0; q < 4; q++) acc[i][j][q] = 0.0f;

    auto ldAB = [&](int s, int kt) {
#pragma unroll
        for (int q = 0; q < 4; q++) {
            int idx = q * 256 + tid;
            int row = idx >> 3, c = idx & 7;
            cp_async16(As + s * STG + row * 72 + c * 8,
                       AH + (size_t)(m0 + row) * K + kt * 64 + c * 8);
        }
#pragma unroll
        for (int q = 0; q < 4; q++) {
            int idx = q * 256 + tid;
            int row = idx >> 3, c = idx & 7;
            cp_async16(Bs + s * STG + row * 72 + c * 8,
                       BmH + (size_t)(n0 + row) * K + kt * 64 + c * 8);
        }
        asm volatile("cp.async.commit_group;\n" ::);
    };

    ldAB(0, 0);
    asm volatile("cp.async.wait_group 0;\n" ::);
    __syncthreads();

    for (int kt = 0; kt < nk; kt++) {
        int s = kt & 1;
        bool more = (kt + 1 < nk);
        if (more) ldAB(s ^ 1, kt + 1);

        const __half* Asb = As + s * STG;
        const __half* Bsb = Bs + s * STG;
#pragma unroll
        for (int kk = 0; kk < 4; kk++) {
            uint32_t af[4][4];
#pragma unroll
            for (int mt = 0; mt < 4; mt++) {
                int row = wr + mt * 16 + g;
                int col = kk * 16 + 2 * t;
                af[mt][0] = *reinterpret_cast<const uint32_t*>(Asb + row * 72 + col);
                af[mt][1] = *reinterpret_cast<const uint32_t*>(Asb + (row + 8) * 72 + col);
                af[mt][2] = *reinterpret_cast<const uint32_t*>(Asb + row * 72 + col + 8);
                af[mt][3] = *reinterpret_cast<const uint32_t*>(Asb + (row + 8) * 72 + col + 8);
            }
            uint32_t bf[4][2];
#pragma unroll
            for (int nt = 0; nt < 4; nt++) {
                int nl = wc + nt * 8 + g;
                int col = kk * 16 + 2 * t;
                bf[nt][0] = *reinterpret_cast<const uint32_t*>(Bsb + nl * 72 + col);
                bf[nt][1] = *reinterpret_cast<const uint32_t*>(Bsb + nl * 72 + col + 8);
            }
#pragma unroll
            for (int mt = 0; mt < 4; mt++)
#pragma unroll
                for (int nt = 0; nt < 4; nt++)
                    mma_f16(acc[mt][nt], af[mt], bf[nt]);
        }
        if (more) asm volatile("cp.async.wait_group 0;\n" ::);
        __syncthreads();
    }

    // epilogue: f -> gmem (fp16) AND stage double-rounded values for local scan
    float* Ys = reinterpret_cast<float*>(smh);   // overlay 128 x 132 fp32
#pragma unroll
    for (int mt = 0; mt < 4; mt++) {
#pragma unroll
        for (int nt = 0; nt < 4; nt++) {
            int rl = wr + mt * 16 + g;
            int ccl = wc + nt * 8 + 2 * t;
            int r0 = m0 + rl;
            __half2 h01 = __floats2half2_rn(acc[mt][nt][0], acc[mt][nt][1]);
            __half2 h23 = __floats2half2_rn(acc[mt][nt][2], acc[mt][nt][3]);
            *reinterpret_cast<__half2*>(F + (size_t)r0 * N + n0 + ccl) = h01;
            *reinterpret_cast<__half2*>(F + (size_t)(r0 + 8) * N + n0 + ccl) = h23;
            float2 v01 = __half22float2(h01);
            float2 v23 = __half22float2(h23);
            *reinterpret_cast<float2*>(Ys + rl * 132 + ccl) = v01;
            *reinterpret_cast<float2*>(Ys + (rl + 8) * 132 + ccl) = v23;
        }
    }
    __syncthreads();

    // local scan: thread -> (col 0..127, chunk 0..1), zero init
    {
        int col = tid & 127, chunk = tid >> 7;
        int ng = n0 + col;
        int p = ng >> 1, c = ng & 1;
        float m11 = g_m11[p], m12 = g_m12[p], m21 = g_dts[p];
        float x1 = 0.0f, x2 = 0.0f;
        const float* base = Ys + (chunk * 64) * 132 + col;
#pragma unroll 8
        for (int j = 0; j < CLEN; j++) {
            float fv = base[j * 132];
            float n1 = fmaf(m11, x1, fmaf(m12, x2, fv));
            float n2 = fmaf(m21, x1, x2);
            x1 = n1; x2 = n2;
        }
        int b = m0 >> 12;
        int ch = ((m0 & 4095) >> 6) + chunk;
        float* cfp = g_cf + ((size_t)(b * 256 + p) * 64 + ch) * 4;
        cfp[c]     = x1;
        cfp[2 + c] = x2;
    }
}

// ---------------------------------------------------------------------------
// Scan phase 2: warp-parallel cross-chunk combine (Kogge-Stone over 32 lanes)
// ---------------------------------------------------------------------------
__global__ void __launch_bounds__(256) scan_combine() {
    const unsigned FULL = 0xFFFFFFFFu;
    int wg = blockIdx.x * 8 + (threadIdx.x >> 5);   // 0..2047
    int lane = threadIdx.x & 31;
    int b = wg >> 8, p = wg & 255;

    float m11 = g_m11[p], m12 = g_m12[p], m21 = g_dts[p];
    float pa = m11, pb = m12, pc = m21, pd = 1.0f;
#pragma unroll
    for (int i = 0; i < 6; i++) {
        float na = fmaf(pa, pa, pb * pc);
        float nb = fmaf(pa, pb, pb * pd);
        float nc = fmaf(pc, pa, pd * pc);
        float nd = fmaf(pc, pb, pd * pd);
        pa = na; pb = nb; pc = nc; pd = nd;
    }

    const float4* cf = reinterpret_cast<const float4*>(g_cf) + (size_t)(b * 256 + p) * 64;
    float4 v0 = cf[2 * lane];
    float4 v1 = cf[2 * lane + 1];

    float w1r = fmaf(pa, v0.x, fmaf(pb, v0.z, v1.x));
    float w1i = fmaf(pa, v0.y, fmaf(pb, v0.w, v1.y));
    float w2r = fmaf(pc, v0.x, fmaf(pd, v0.z, v1.z));
    float w2i = fmaf(pc, v0.y, fmaf(pd, v0.w, v1.w));
    float ma = fmaf(pa, pa, pb * pc), mb = fmaf(pa, pb, pb * pd);
    float mc = fmaf(pc, pa, pd * pc), md = fmaf(pc, pb, pd * pd);

#pragma unroll
    for (int d = 1; d < 32; d <<= 1) {
        float oa = __shfl_up_sync(FULL, ma, d);
        float ob = __shfl_up_sync(FULL, mb, d);
        float oc = __shfl_up_sync(FULL, mc, d);
        float od = __shfl_up_sync(FULL, md, d);
        float o1r = __shfl_up_sync(FULL, w1r, d);
        float o1i = __shfl_up_sync(FULL, w1i, d);
        float o2r = __shfl_up_sync(FULL, w2r, d);
        float o2i = __shfl_up_sync(FULL, w2i, d);
        if (lane >= d) {
            w1r = fmaf(ma, o1r, fmaf(mb, o2r, w1r));
            w1i = fmaf(ma, o1i, fmaf(mb, o2i, w1i));
            w2r = fmaf(mc, o1r, fmaf(md, o2r, w2r));
            w2i = fmaf(mc, o1i, fmaf(md, o2i, w2i));
            float na = fmaf(ma, oa, mb * oc), nb = fmaf(ma, ob, mb * od);
            float nc = fmaf(mc, oa, md * oc), nd = fmaf(mc, ob, md * od);
            ma = na; mb = nb; mc = nc; md = nd;
        }
    }

    float e1r = __shfl_up_sync(FULL, w1r, 1);
    float e1i = __shfl_up_sync(FULL, w1i, 1);
    float e2r = __shfl_up_sync(FULL, w2r, 1);
    float e2i = __shfl_up_sync(FULL, w2i, 1);
    if (lane == 0) { e1r = e1i = e2r = e2i = 0.0f; }

    float4* gi = reinterpret_cast<float4*>(g_init) + (size_t)(b * 256 + p) * 64;
    gi[2 * lane] = make_float4(e1r, e1i, e2r, e2i);
    gi[2 * lane + 1] = make_float4(
        fmaf(pa, e1r, fmaf(pb, e2r, v0.x)),
        fmaf(pa, e1i, fmaf(pb, e2i, v0.y)),
        fmaf(pc, e1r, fmaf(pd, e2r, v0.z)),
        fmaf(pc, e1i, fmaf(pd, e2i, v0.w)));
}

// ---------------------------------------------------------------------------
// Scan phase 3: FOUR chunks per thread (independent chains -> 4x MLP/ILP)
// grid 128: block = (b, chunk-quad); thread = column pair p
// ---------------------------------------------------------------------------
__global__ void scan_final4() {
    int b = blockIdx.x >> 4;
    int q = blockIdx.x & 15;
    int ch0 = q * 4;
    int p = threadIdx.x;
    float m11 = g_m11[p], m12 = g_m12[p], m21 = g_dts[p];
    const float4* gi = reinterpret_cast<const float4*>(g_init) + (size_t)(b * 256 + p) * 64;
    float4 iv0 = gi[ch0], iv1 = gi[ch0 + 1], iv2 = gi[ch0 + 2], iv3 = gi[ch0 + 3];
    float x1r0 = iv0.x, x1i0 = iv0.y, x2r0 = iv0.z, x2i0 = iv0.w;
    float x1r1 = iv1.x, x1i1 = iv1.y, x2r1 = iv1.z, x2i1 = iv1.w;
    float x1r2 = iv2.x, x1i2 = iv2.y, x2r2 = iv2.z, x2i2 = iv2.w;
    float x1r3 = iv3.x, x1i3 = iv3.y, x2r3 = iv3.z, x2i3 = iv3.w;
    const __half2* f0 = reinterpret_cast<const __half2*>(g_fh)
                        + ((size_t)(b * Lc + ch0 * CLEN)) * 256 + p;
    const __half2* f1 = f0 + (size_t)CLEN * 256;
    const __half2* f2 = f1 + (size_t)CLEN * 256;
    const __half2* f3 = f2 + (size_t)CLEN * 256;
    __half2* y0 = reinterpret_cast<__half2*>(g_ysh)
                  + ((size_t)(b * Lc + ch0 * CLEN)) * 256 + p;
    __half2* y1 = y0 + (size_t)CLEN * 256;
    __half2* y2 = y1 + (size_t)CLEN * 256;
    __half2* y3 = y2 + (size_t)CLEN * 256;
#pragma unroll 4
    for (int j = 0; j < CLEN; j++) {
        float2 a = __half22float2(f0[(size_t)j * 256]);
        float2 bb = __half22float2(f1[(size_t)j * 256]);
        float2 cc = __half22float2(f2[(size_t)j * 256]);
        float2 dd = __half22float2(f3[(size_t)j * 256]);
        float n1r0 = fmaf(m11, x1r0, fmaf(m12, x2r0, a.x));
        float n2r0 = fmaf(m21, x1r0, x2r0);
        float n1i0 = fmaf(m11, x1i0, fmaf(m12, x2i0, a.y));
        float n2i0 = fmaf(m21, x1i0, x2i0);
        float n1r1 = fmaf(m11, x1r1, fmaf(m12, x2r1, bb.x));
        float n2r1 = fmaf(m21, x1r1, x2r1);
        float n1i1 = fmaf(m11, x1i1, fmaf(m12, x2i1, bb.y));
        float n2i1 = fmaf(m21, x1i1, x2i1);
        float n1r2 = fmaf(m11, x1r2, fmaf(m12, x2r2, cc.x));
        float n2r2 = fmaf(m21, x1r2, x2r2);
        float n1i2 = fmaf(m11, x1i2, fmaf(m12, x2i2, cc.y));
        float n2i2 = fmaf(m21, x1i2, x2i2);
        float n1r3 = fmaf(m11, x1r3, fmaf(m12, x2r3, dd.x));
        float n2r3 = fmaf(m21, x1r3, x2r3);
        float n1i3 = fmaf(m11, x1i3, fmaf(m12, x2i3, dd.y));
        float n2i3 = fmaf(m21, x1i3, x2i3);
        x1r0 = n1r0; x2r0 = n2r0; x1i0 = n1i0; x2i0 = n2i0;
        x1r1 = n1r1; x2r1 = n2r1; x1i1 = n1i1; x2i1 = n2i1;
        x1r2 = n1r2; x2r2 = n2r2; x1i2 = n1i2; x2i2 = n2i2;
        x1r3 = n1r3; x2r3 = n2r3; x1i3 = n1i3; x2i3 = n2i3;
        y0[(size_t)j * 256] = __floats2half2_rn(x2r0, x2i0);
        y1[(size_t)j * 256] = __floats2half2_rn(x2r1, x2i1);
        y2[(size_t)j * 256] = __floats2half2_rn(x2r2, x2i2);
        y3[(size_t)j * 256] = __floats2half2_rn(x2r3, x2i3);
    }
}

// ---------------------------------------------------------------------------
// GEMM2: out = ys @ Cop^T + D*u  (M=32768, N=256, K=512); k-tile 64, 2-stage
// ---------------------------------------------------------------------------
__global__ void __launch_bounds__(256, 2)
gemm2_f16(const __half* __restrict__ AH, const __half* __restrict__ BmH,
          float* __restrict__ Out, const __half* __restrict__ UH,
          const float* __restrict__ Dv) {
    constexpr int N = 256, K = 512, nk = K / 64;
    extern __shared__ __half smh[];
    __half* As = smh;                 // 2 stages * STG
    __half* Bs = smh + 2 * STG;

    const int tid  = threadIdx.x;
    const int lane = tid & 31, warp = tid >> 5;
    const int g = lane >> 2, t = lane & 3;
    const int wr = (warp & 1) * 64, wc = (warp >> 1) * 32;
    const int m0 = blockIdx.y * 128, n0 = blockIdx.x * 128;

    float acc[4][4][4];
#pragma unroll
    for (int i = 0; i < 4; i++)
#pragma unroll
        for (int j = 0; j < 4; j++)
#pragma unroll
            for (int q = 0; q < 4; q++) acc[i][j][q] = 0.0f;

    auto ldAB = [&](int s, int kt) {
#pragma unroll
        for (int q = 0; q < 4; q++) {
            int idx = q * 256 + tid;
            int row = idx >> 3, c = idx & 7;
            cp_async16(As + s * STG + row * 72 + c * 8,
                       AH + (size_t)(m0 + row) * K + kt * 64 + c * 8);
        }
#pragma unroll
        for (int q = 0; q < 4; q++) {
            int idx = q * 256 + tid;
            int row = idx >> 3, c = idx & 7;
            cp_async16(Bs + s * STG + row * 72 + c * 8,
                       BmH + (size_t)(n0 + row) * K + kt * 64 + c * 8);
        }
        asm volatile("cp.async.commit_group;\n" ::);
    };

    ldAB(0, 0);
    asm volatile("cp.async.wait_group 0;\n" ::);
    __syncthreads();

    for (int kt = 0; kt < nk; kt++) {
        int s = kt & 1;
        bool more = (kt + 1 < nk);
        if (more) ldAB(s ^ 1, kt + 1);

        const __half* Asb = As + s * STG;
        const __half* Bsb = Bs + s * STG;
#pragma unroll
        for (int kk = 0; kk < 4; kk++) {
            uint32_t af[4][4];
#pragma unroll
            for (int mt = 0; mt < 4; mt++) {
                int row = wr + mt * 16 + g;
                int col = kk * 16 + 2 * t;
                af[mt][0] = *reinterpret_cast<const uint32_t*>(Asb + row * 72 + col);
                af[mt][1] = *reinterpret_cast<const uint32_t*>(Asb + (row + 8) * 72 + col);
                af[mt][2] = *reinterpret_cast<const uint32_t*>(Asb + row * 72 + col + 8);
                af[mt][3] = *reinterpret_cast<const uint32_t*>(Asb + (row + 8) * 72 + col + 8);
            }
            uint32_t bf[4][2];
#pragma unroll
            for (int nt = 0; nt < 4; nt++) {
                int nl = wc + nt * 8 + g;
                int col = kk * 16 + 2 * t;
                bf[nt][0] = *reinterpret_cast<const uint32_t*>(Bsb + nl * 72 + col);
                bf[nt][1] = *reinterpret_cast<const uint32_t*>(Bsb + nl * 72 + col + 8);
            }
#pragma unroll
            for (int mt = 0; mt < 4; mt++)
#pragma unroll
                for (int nt = 0; nt < 4; nt++)
                    mma_f16(acc[mt][nt], af[mt], bf[nt]);
        }
        if (more) asm volatile("cp.async.wait_group 0;\n" ::);
        __syncthreads();
    }

    // epilogue: + D*u (u fp16), write out
#pragma unroll
    for (int mt = 0; mt < 4; mt++) {
#pragma unroll
        for (int nt = 0; nt < 4; nt++) {
            int r0 = m0 + wr + mt * 16 + g;
            int cc = n0 + wc + nt * 8 + 2 * t;
            float d0 = Dv[cc], d1 = Dv[cc + 1];
            float2 u0 = __half22float2(
                *reinterpret_cast<const __half2*>(UH + (size_t)r0 * 256 + cc));
            float2 u1 = __half22float2(
                *reinterpret_cast<const __half2*>(UH + (size_t)(r0 + 8) * 256 + cc));
            float v0 = fmaf(d0, u0.x, acc[mt][nt][0]);
            float v1 = fmaf(d1, u0.y, acc[mt][nt][1]);
            float v2 = fmaf(d0, u1.x, acc[mt][nt][2]);
            float v3 = fmaf(d1, u1.y, acc[mt][nt][3]);
            *reinterpret_cast<float2*>(Out + (size_t)r0 * N + cc) = make_float2(v0, v1);
            *reinterpret_cast<float2*>(Out + (size_t)(r0 + 8) * N + cc) = make_float2(v2, v3);
        }
    }
}

// ---------------------------------------------------------------------------
extern "C" void kernel_launch(void* const* d_in, const int* in_sizes, int n_in,
                              void* d_out, int out_size) {
    const float* u  = (const float*)d_in[0];
    const float* Ad = (const float*)d_in[1];
    const float* Gd = (const float*)d_in[2];
    const float* dt = (const float*)d_in[3];
    const float* Bm = (const float*)d_in[4];
    const float* Cm = (const float*)d_in[5];
    const float* Dv = (const float*)d_in[6];
    float* out = (float*)d_out;

    __half *uh, *fptr, *ysptr, *bop, *cop;
    cudaGetSymbolAddress((void**)&uh,    g_uh);
    cudaGetSymbolAddress((void**)&fptr,  g_fh);
    cudaGetSymbolAddress((void**)&ysptr, g_ysh);
    cudaGetSymbolAddress((void**)&bop,   g_BopH);
    cudaGetSymbolAddress((void**)&cop,   g_CopH);

    const int smem_pipe = 4 * STG * 2;              // 73728 (2 stages A+B, k-tile 64)
    cudaFuncSetAttribute(gemm1_f16,
                         cudaFuncAttributeMaxDynamicSharedMemorySize, smem_pipe);
    cudaFuncSetAttribute(gemm2_f16,
                         cudaFuncAttributeMaxDynamicSharedMemorySize, smem_pipe);

    u2h_kernel<<<Mrows * 256 / (256 * 8), 256>>>(u);
    prep_kernel<<<256, 512>>>(Ad, Gd, dt, Bm, Cm);

    // GEMM1 + fused local scan: f = u @ Bop^T (fp16 out), chunk states -> g_cf
    gemm1_f16<<<dim3(4, 256), 256, smem_pipe>>>(uh, bop, fptr);

    scan_combine<<<256, 256>>>();

    // final scan: ys = scan(f), fp16 in/out, 4 chunks per thread
    scan_final4<<<Bc * NCHUNK / 4, 256>>>();

    // GEMM2: out = ys @ Cop^T + D*u (u fp16)
    gemm2_f16<<<dim3(2, 256), 256, smem_pipe>>>(ysptr, cop, out, uh, Dv);
}

// round 17
// speedup vs baseline: 1.1528x; 1.0546x over previous
#include <cuda_runtime.h>
#include <cuda_fp16.h>
#include <cstdint>

// Problem constants
constexpr int Bc = 8, Lc = 4096;
constexpr int Mrows = Bc * Lc;          // 32768
constexpr int NCHUNK = 64, CLEN = 64;   // 64 chunks of 64 steps

// Scratch (static device arrays -- no allocation allowed)
__device__ __half g_uh [(size_t)Mrows * 256]; // u  (fp16): [bl][h]
__device__ __half g_fh [(size_t)Mrows * 512]; // f  (fp16): [bl][2p+c]
__device__ __half g_ysh[(size_t)Mrows * 512]; // ys (fp16), same layout
__device__ __half g_BopH[512 * 256];          // GEMM1 B, [n=2p+c][k=h]
__device__ __half g_CopH[256 * 512];          // GEMM2 B, [n=h][k=2p+c]
__device__ float  g_m11[256], g_m12[256], g_dts[256];
__device__ float  g_cf  [Bc * 256 * NCHUNK * 4]; // [b][p][ch] float4
__device__ float  g_init[Bc * 256 * NCHUNK * 4];

constexpr int STG = 9216;   // halves per operand stage (128 rows x 72, k-tile 64)

__device__ __forceinline__ void cp_async16(void* smem, const void* gmem) {
    uint32_t s = (uint32_t)__cvta_generic_to_shared(smem);
    asm volatile("cp.async.ca.shared.global [%0], [%1], 16;\n" :: "r"(s), "l"(gmem));
}

__device__ __forceinline__ void mma_f16(float c[4], const uint32_t a[4], const uint32_t b[2]) {
    asm volatile(
        "mma.sync.aligned.m16n8k16.row.col.f32.f16.f16.f32 "
        "{%0,%1,%2,%3}, {%4,%5,%6,%7}, {%8,%9}, {%0,%1,%2,%3};\n"
        : "+f"(c[0]), "+f"(c[1]), "+f"(c[2]), "+f"(c[3])
        : "r"(a[0]), "r"(a[1]), "r"(a[2]), "r"(a[3]), "r"(b[0]), "r"(b[1]));
}

__device__ __forceinline__ void ldsm4(uint32_t& r0, uint32_t& r1, uint32_t& r2,
                                      uint32_t& r3, uint32_t addr) {
    asm volatile("ldmatrix.sync.aligned.m8n8.x4.shared.b16 {%0,%1,%2,%3}, [%4];"
                 : "=r"(r0), "=r"(r1), "=r"(r2), "=r"(r3) : "r"(addr));
}

// ---------------------------------------------------------------------------
// u -> fp16 pre-pass: 8M floats, 8 per thread
// ---------------------------------------------------------------------------
__global__ void u2h_kernel(const float* __restrict__ U) {
    size_t i = ((size_t)blockIdx.x * 256 + threadIdx.x) * 8;
    float4 a = *reinterpret_cast<const float4*>(U + i);
    float4 b = *reinterpret_cast<const float4*>(U + i + 4);
    __half2 h0 = __floats2half2_rn(a.x, a.y);
    __half2 h1 = __floats2half2_rn(a.z, a.w);
    __half2 h2 = __floats2half2_rn(b.x, b.y);
    __half2 h3 = __floats2half2_rn(b.z, b.w);
    uint4 pk;
    pk.x = *reinterpret_cast<uint32_t*>(&h0);
    pk.y = *reinterpret_cast<uint32_t*>(&h1);
    pk.z = *reinterpret_cast<uint32_t*>(&h2);
    pk.w = *reinterpret_cast<uint32_t*>(&h3);
    *reinterpret_cast<uint4*>(g_uh + i) = pk;
}

// ---------------------------------------------------------------------------
// Prep: per-p recurrence params + fp16 operand matrices (B stored [n][k])
// ---------------------------------------------------------------------------
__global__ void prep_kernel(const float* __restrict__ Ad, const float* __restrict__ Gd,
                            const float* __restrict__ dt, const float* __restrict__ Bm,
                            const float* __restrict__ Cm) {
    int h = blockIdx.x;          // 0..255
    int n = threadIdx.x;         // 0..511
    int p = n >> 1;
    int c = n & 1;
    float dts = 1.0f / (1.0f + expf(-dt[p]));
    float G = fmaxf(Gd[p], dts * Ad[p]);
    float A = fmaxf(Ad[p], 0.25f * G * G);

    g_BopH[n * 256 + h] = __float2half(dts * Bm[p * 512 + h * 2 + c]);
    float cv = Cm[h * 512 + p * 2 + c];
    g_CopH[h * 512 + n] = __float2half(c ? -cv : cv);

    if (h == 0 && c == 0) {
        g_m11[p] = 1.0f - dts * G;
        g_m12[p] = -dts * A;
        g_dts[p] = dts;          // m21; m22 == 1
    }
}

// ---------------------------------------------------------------------------
// GEMM1 (+ fused local scan): f = u @ Bop^T  (M=32768, N=512, K=256)
// k-tile 64, 2-stage cp.async, ldmatrix fragment loads.
// ---------------------------------------------------------------------------
__global__ void __launch_bounds__(256, 2)
gemm1_f16(const __half* __restrict__ AH, const __half* __restrict__ BmH,
          __half* __restrict__ F) {
    constexpr int N = 512, K = 256, nk = K / 64;
    extern __shared__ __half smh[];
    __half* As = smh;                 // 2 stages * STG
    __half* Bs = smh + 2 * STG;
    const uint32_t sb = (uint32_t)__cvta_generic_to_shared(smh);

    const int tid  = threadIdx.x;
    const int lane = tid & 31, warp = tid >> 5;
    const int g = lane >> 2, t = lane & 3;
    const int wr = (warp & 1) * 64, wc = (warp >> 1) * 32;
    const int m0 = blockIdx.y * 128, n0 = blockIdx.x * 128;

    // ldmatrix per-lane address components (byte offsets within a stage)
    const uint32_t ldmA = (uint32_t)((((lane >> 3) & 1) * 8 + (lane & 7)) * 144
                                     + (lane >> 4) * 16);
    const uint32_t ldmB = (uint32_t)((((lane >> 4) & 1) * 8 + (lane & 7)) * 144
                                     + ((lane >> 3) & 1) * 16);

    float acc[4][4][4];
#pragma unroll
    for (int i = 0; i < 4; i++)
#pragma unroll
        for (int j = 0; j < 4; j++)
#pragma unroll
            for (int q = 0; q < 4; q++) acc[i][j][q] = 0.0f;

    auto ldAB = [&](int s, int kt) {
#pragma unroll
        for (int q = 0; q < 4; q++) {
            int idx = q * 256 + tid;
            int row = idx >> 3, c = idx & 7;
            cp_async16(As + s * STG + row * 72 + c * 8,
                       AH + (size_t)(m0 + row) * K + kt * 64 + c * 8);
        }
#pragma unroll
        for (int q = 0; q < 4; q++) {
            int idx = q * 256 + tid;
            int row = idx >> 3, c = idx & 7;
            cp_async16(Bs + s * STG + row * 72 + c * 8,
                       BmH + (size_t)(n0 + row) * K + kt * 64 + c * 8);
        }
        asm volatile("cp.async.commit_group;\n" ::);
    };

    ldAB(0, 0);
    asm volatile("cp.async.wait_group 0;\n" ::);
    __syncthreads();

    for (int kt = 0; kt < nk; kt++) {
        int s = kt & 1;
        bool more = (kt + 1 < nk);
        if (more) ldAB(s ^ 1, kt + 1);

        const uint32_t aBase = sb + (uint32_t)(s * STG * 2) + (uint32_t)(wr * 144) + ldmA;
        const uint32_t bBase = sb + (uint32_t)((2 * STG + s * STG) * 2)
                             + (uint32_t)(wc * 144) + ldmB;
#pragma unroll
        for (int kk = 0; kk < 4; kk++) {
            uint32_t af[4][4];
#pragma unroll
            for (int mt = 0; mt < 4; mt++)
                ldsm4(af[mt][0], af[mt][1], af[mt][2], af[mt][3],
                      aBase + mt * (16 * 144) + kk * 32);
            uint32_t bf[4][2];
#pragma unroll
            for (int ntp = 0; ntp < 2; ntp++) {
                uint32_t r0, r1, r2, r3;
                ldsm4(r0, r1, r2, r3, bBase + ntp * (16 * 144) + kk * 32);
                bf[2 * ntp][0] = r0; bf[2 * ntp][1] = r1;
                bf[2 * ntp + 1][0] = r2; bf[2 * ntp + 1][1] = r3;
            }
#pragma unroll
            for (int mt = 0; mt < 4; mt++)
#pragma unroll
                for (int nt = 0; nt < 4; nt++)
                    mma_f16(acc[mt][nt], af[mt], bf[nt]);
        }
        if (more) asm volatile("cp.async.wait_group 0;\n" ::);
        __syncthreads();
    }

    // epilogue: f -> gmem (fp16) AND stage double-rounded values for local scan
    float* Ys = reinterpret_cast<float*>(smh);   // overlay 128 x 132 fp32
#pragma unroll
    for (int mt = 0; mt < 4; mt++) {
#pragma unroll
        for (int nt = 0; nt < 4; nt++) {
            int rl = wr + mt * 16 + g;
            int ccl = wc + nt * 8 + 2 * t;
            int r0 = m0 + rl;
            __half2 h01 = __floats2half2_rn(acc[mt][nt][0], acc[mt][nt][1]);
            __half2 h23 = __floats2half2_rn(acc[mt][nt][2], acc[mt][nt][3]);
            *reinterpret_cast<__half2*>(F + (size_t)r0 * N + n0 + ccl) = h01;
            *reinterpret_cast<__half2*>(F + (size_t)(r0 + 8) * N + n0 + ccl) = h23;
            float2 v01 = __half22float2(h01);
            float2 v23 = __half22float2(h23);
            *reinterpret_cast<float2*>(Ys + rl * 132 + ccl) = v01;
            *reinterpret_cast<float2*>(Ys + (rl + 8) * 132 + ccl) = v23;
        }
    }
    __syncthreads();

    // local scan: thread -> (col 0..127, chunk 0..1), zero init
    {
        int col = tid & 127, chunk = tid >> 7;
        int ng = n0 + col;
        int p = ng >> 1, c = ng & 1;
        float m11 = g_m11[p], m12 = g_m12[p], m21 = g_dts[p];
        float x1 = 0.0f, x2 = 0.0f;
        const float* base = Ys + (chunk * 64) * 132 + col;
#pragma unroll 8
        for (int j = 0; j < CLEN; j++) {
            float fv = base[j * 132];
            float n1 = fmaf(m11, x1, fmaf(m12, x2, fv));
            float n2 = fmaf(m21, x1, x2);
            x1 = n1; x2 = n2;
        }
        int b = m0 >> 12;
        int ch = ((m0 & 4095) >> 6) + chunk;
        float* cfp = g_cf + ((size_t)(b * 256 + p) * 64 + ch) * 4;
        cfp[c]     = x1;
        cfp[2 + c] = x2;
    }
}

// ---------------------------------------------------------------------------
// Scan phase 2: warp-parallel cross-chunk combine (Kogge-Stone over 32 lanes)
// ---------------------------------------------------------------------------
__global__ void __launch_bounds__(256) scan_combine() {
    const unsigned FULL = 0xFFFFFFFFu;
    int wg = blockIdx.x * 8 + (threadIdx.x >> 5);   // 0..2047
    int lane = threadIdx.x & 31;
    int b = wg >> 8, p = wg & 255;

    float m11 = g_m11[p], m12 = g_m12[p], m21 = g_dts[p];
    float pa = m11, pb = m12, pc = m21, pd = 1.0f;
#pragma unroll
    for (int i = 0; i < 6; i++) {
        float na = fmaf(pa, pa, pb * pc);
        float nb = fmaf(pa, pb, pb * pd);
        float nc = fmaf(pc, pa, pd * pc);
        float nd = fmaf(pc, pb, pd * pd);
        pa = na; pb = nb; pc = nc; pd = nd;
    }

    const float4* cf = reinterpret_cast<const float4*>(g_cf) + (size_t)(b * 256 + p) * 64;
    float4 v0 = cf[2 * lane];
    float4 v1 = cf[2 * lane + 1];

    float w1r = fmaf(pa, v0.x, fmaf(pb, v0.z, v1.x));
    float w1i = fmaf(pa, v0.y, fmaf(pb, v0.w, v1.y));
    float w2r = fmaf(pc, v0.x, fmaf(pd, v0.z, v1.z));
    float w2i = fmaf(pc, v0.y, fmaf(pd, v0.w, v1.w));
    float ma = fmaf(pa, pa, pb * pc), mb = fmaf(pa, pb, pb * pd);
    float mc = fmaf(pc, pa, pd * pc), md = fmaf(pc, pb, pd * pd);

#pragma unroll
    for (int d = 1; d < 32; d <<= 1) {
        float oa = __shfl_up_sync(FULL, ma, d);
        float ob = __shfl_up_sync(FULL, mb, d);
        float oc = __shfl_up_sync(FULL, mc, d);
        float od = __shfl_up_sync(FULL, md, d);
        float o1r = __shfl_up_sync(FULL, w1r, d);
        float o1i = __shfl_up_sync(FULL, w1i, d);
        float o2r = __shfl_up_sync(FULL, w2r, d);
        float o2i = __shfl_up_sync(FULL, w2i, d);
        if (lane >= d) {
            w1r = fmaf(ma, o1r, fmaf(mb, o2r, w1r));
            w1i = fmaf(ma, o1i, fmaf(mb, o2i, w1i));
            w2r = fmaf(mc, o1r, fmaf(md, o2r, w2r));
            w2i = fmaf(mc, o1i, fmaf(md, o2i, w2i));
            float na = fmaf(ma, oa, mb * oc), nb = fmaf(ma, ob, mb * od);
            float nc = fmaf(mc, oa, md * oc), nd = fmaf(mc, ob, md * od);
            ma = na; mb = nb; mc = nc; md = nd;
        }
    }

    float e1r = __shfl_up_sync(FULL, w1r, 1);
    float e1i = __shfl_up_sync(FULL, w1i, 1);
    float e2r = __shfl_up_sync(FULL, w2r, 1);
    float e2i = __shfl_up_sync(FULL, w2i, 1);
    if (lane == 0) { e1r = e1i = e2r = e2i = 0.0f; }

    float4* gi = reinterpret_cast<float4*>(g_init) + (size_t)(b * 256 + p) * 64;
    gi[2 * lane] = make_float4(e1r, e1i, e2r, e2i);
    gi[2 * lane + 1] = make_float4(
        fmaf(pa, e1r, fmaf(pb, e2r, v0.x)),
        fmaf(pa, e1i, fmaf(pb, e2i, v0.y)),
        fmaf(pc, e1r, fmaf(pd, e2r, v0.z)),
        fmaf(pc, e1i, fmaf(pd, e2i, v0.w)));
}

// ---------------------------------------------------------------------------
// Scan phase 3: FOUR chunks per thread (independent chains -> 4x MLP/ILP)
// ---------------------------------------------------------------------------
__global__ void scan_final4() {
    int b = blockIdx.x >> 4;
    int q = blockIdx.x & 15;
    int ch0 = q * 4;
    int p = threadIdx.x;
    float m11 = g_m11[p], m12 = g_m12[p], m21 = g_dts[p];
    const float4* gi = reinterpret_cast<const float4*>(g_init) + (size_t)(b * 256 + p) * 64;
    float4 iv0 = gi[ch0], iv1 = gi[ch0 + 1], iv2 = gi[ch0 + 2], iv3 = gi[ch0 + 3];
    float x1r0 = iv0.x, x1i0 = iv0.y, x2r0 = iv0.z, x2i0 = iv0.w;
    float x1r1 = iv1.x, x1i1 = iv1.y, x2r1 = iv1.z, x2i1 = iv1.w;
    float x1r2 = iv2.x, x1i2 = iv2.y, x2r2 = iv2.z, x2i2 = iv2.w;
    float x1r3 = iv3.x, x1i3 = iv3.y, x2r3 = iv3.z, x2i3 = iv3.w;
    const __half2* f0 = reinterpret_cast<const __half2*>(g_fh)
                        + ((size_t)(b * Lc + ch0 * CLEN)) * 256 + p;
    const __half2* f1 = f0 + (size_t)CLEN * 256;
    const __half2* f2 = f1 + (size_t)CLEN * 256;
    const __half2* f3 = f2 + (size_t)CLEN * 256;
    __half2* y0 = reinterpret_cast<__half2*>(g_ysh)
                  + ((size_t)(b * Lc + ch0 * CLEN)) * 256 + p;
    __half2* y1 = y0 + (size_t)CLEN * 256;
    __half2* y2 = y1 + (size_t)CLEN * 256;
    __half2* y3 = y2 + (size_t)CLEN * 256;
#pragma unroll 4
    for (int j = 0; j < CLEN; j++) {
        float2 a = __half22float2(f0[(size_t)j * 256]);
        float2 bb = __half22float2(f1[(size_t)j * 256]);
        float2 cc = __half22float2(f2[(size_t)j * 256]);
        float2 dd = __half22float2(f3[(size_t)j * 256]);
        float n1r0 = fmaf(m11, x1r0, fmaf(m12, x2r0, a.x));
        float n2r0 = fmaf(m21, x1r0, x2r0);
        float n1i0 = fmaf(m11, x1i0, fmaf(m12, x2i0, a.y));
        float n2i0 = fmaf(m21, x1i0, x2i0);
        float n1r1 = fmaf(m11, x1r1, fmaf(m12, x2r1, bb.x));
        float n2r1 = fmaf(m21, x1r1, x2r1);
        float n1i1 = fmaf(m11, x1i1, fmaf(m12, x2i1, bb.y));
        float n2i1 = fmaf(m21, x1i1, x2i1);
        float n1r2 = fmaf(m11, x1r2, fmaf(m12, x2r2, cc.x));
        float n2r2 = fmaf(m21, x1r2, x2r2);
        float n1i2 = fmaf(m11, x1i2, fmaf(m12, x2i2, cc.y));
        float n2i2 = fmaf(m21, x1i2, x2i2);
        float n1r3 = fmaf(m11, x1r3, fmaf(m12, x2r3, dd.x));
        float n2r3 = fmaf(m21, x1r3, x2r3);
        float n1i3 = fmaf(m11, x1i3, fmaf(m12, x2i3, dd.y));
        float n2i3 = fmaf(m21, x1i3, x2i3);
        x1r0 = n1r0; x2r0 = n2r0; x1i0 = n1i0; x2i0 = n2i0;
        x1r1 = n1r1; x2r1 = n2r1; x1i1 = n1i1; x2i1 = n2i1;
        x1r2 = n1r2; x2r2 = n2r2; x1i2 = n1i2; x2i2 = n2i2;
        x1r3 = n1r3; x2r3 = n2r3; x1i3 = n1i3; x2i3 = n2i3;
        y0[(size_t)j * 256] = __floats2half2_rn(x2r0, x2i0);
        y1[(size_t)j * 256] = __floats2half2_rn(x2r1, x2i1);
        y2[(size_t)j * 256] = __floats2half2_rn(x2r2, x2i2);
        y3[(size_t)j * 256] = __floats2half2_rn(x2r3, x2i3);
    }
}

// ---------------------------------------------------------------------------
// GEMM2: out = ys @ Cop^T + D*u  (M=32768, N=256, K=512); k-tile 64, ldmatrix
// ---------------------------------------------------------------------------
__global__ void __launch_bounds__(256, 2)
gemm2_f16(const __half* __restrict__ AH, const __half* __restrict__ BmH,
          float* __restrict__ Out, const __half* __restrict__ UH,
          const float* __restrict__ Dv) {
    constexpr int N = 256, K = 512, nk = K / 64;
    extern __shared__ __half smh[];
    __half* As = smh;                 // 2 stages * STG
    __half* Bs = smh + 2 * STG;
    const uint32_t sb = (uint32_t)__cvta_generic_to_shared(smh);

    const int tid  = threadIdx.x;
    const int lane = tid & 31, warp = tid >> 5;
    const int g = lane >> 2, t = lane & 3;
    const int wr = (warp & 1) * 64, wc = (warp >> 1) * 32;
    const int m0 = blockIdx.y * 128, n0 = blockIdx.x * 128;

    const uint32_t ldmA = (uint32_t)((((lane >> 3) & 1) * 8 + (lane & 7)) * 144
                                     + (lane >> 4) * 16);
    const uint32_t ldmB = (uint32_t)((((lane >> 4) & 1) * 8 + (lane & 7)) * 144
                                     + ((lane >> 3) & 1) * 16);

    float acc[4][4][4];
#pragma unroll
    for (int i = 0; i < 4; i++)
#pragma unroll
        for (int j = 0; j < 4; j++)
#pragma unroll
            for (int q = 0; q < 4; q++) acc[i][j][q] = 0.0f;

    auto ldAB = [&](int s, int kt) {
#pragma unroll
        for (int q = 0; q < 4; q++) {
            int idx = q * 256 + tid;
            int row = idx >> 3, c = idx & 7;
            cp_async16(As + s * STG + row * 72 + c * 8,
                       AH + (size_t)(m0 + row) * K + kt * 64 + c * 8);
        }
#pragma unroll
        for (int q = 0; q < 4; q++) {
            int idx = q * 256 + tid;
            int row = idx >> 3, c = idx & 7;
            cp_async16(Bs + s * STG + row * 72 + c * 8,
                       BmH + (size_t)(n0 + row) * K + kt * 64 + c * 8);
        }
        asm volatile("cp.async.commit_group;\n" ::);
    };

    ldAB(0, 0);
    asm volatile("cp.async.wait_group 0;\n" ::);
    __syncthreads();

    for (int kt = 0; kt < nk; kt++) {
        int s = kt & 1;
        bool more = (kt + 1 < nk);
        if (more) ldAB(s ^ 1, kt + 1);

        const uint32_t aBase = sb + (uint32_t)(s * STG * 2) + (uint32_t)(wr * 144) + ldmA;
        const uint32_t bBase = sb + (uint32_t)((2 * STG + s * STG) * 2)
                             + (uint32_t)(wc * 144) + ldmB;
#pragma unroll
        for (int kk = 0; kk < 4; kk++) {
            uint32_t af[4][4];
#pragma unroll
            for (int mt = 0; mt < 4; mt++)
                ldsm4(af[mt][0], af[mt][1], af[mt][2], af[mt][3],
                      aBase + mt * (16 * 144) + kk * 32);
            uint32_t bf[4][2];
#pragma unroll
            for (int ntp = 0; ntp < 2; ntp++) {
                uint32_t r0, r1, r2, r3;
                ldsm4(r0, r1, r2, r3, bBase + ntp * (16 * 144) + kk * 32);
                bf[2 * ntp][0] = r0; bf[2 * ntp][1] = r1;
                bf[2 * ntp + 1][0] = r2; bf[2 * ntp + 1][1] = r3;
            }
#pragma unroll
            for (int mt = 0; mt < 4; mt++)
#pragma unroll
                for (int nt = 0; nt < 4; nt++)
                    mma_f16(acc[mt][nt], af[mt], bf[nt]);
        }
        if (more) asm volatile("cp.async.wait_group 0;\n" ::);
        __syncthreads();
    }

    // epilogue: + D*u (u fp16), write out
#pragma unroll
    for (int mt = 0; mt < 4; mt++) {
#pragma unroll
        for (int nt = 0; nt < 4; nt++) {
            int r0 = m0 + wr + mt * 16 + g;
            int cc = n0 + wc + nt * 8 + 2 * t;
            float d0 = Dv[cc], d1 = Dv[cc + 1];
            float2 u0 = __half22float2(
                *reinterpret_cast<const __half2*>(UH + (size_t)r0 * 256 + cc));
            float2 u1 = __half22float2(
                *reinterpret_cast<const __half2*>(UH + (size_t)(r0 + 8) * 256 + cc));
            float v0 = fmaf(d0, u0.x, acc[mt][nt][0]);
            float v1 = fmaf(d1, u0.y, acc[mt][nt][1]);
            float v2 = fmaf(d0, u1.x, acc[mt][nt][2]);
            float v3 = fmaf(d1, u1.y, acc[mt][nt][3]);
            *reinterpret_cast<float2*>(Out + (size_t)r0 * N + cc) = make_float2(v0, v1);
            *reinterpret_cast<float2*>(Out + (size_t)(r0 + 8) * N + cc) = make_float2(v2, v3);
        }
    }
}

// ---------------------------------------------------------------------------
extern "C" void kernel_launch(void* const* d_in, const int* in_sizes, int n_in,
                              void* d_out, int out_size) {
    const float* u  = (const float*)d_in[0];
    const float* Ad = (const float*)d_in[1];
    const float* Gd = (const float*)d_in[2];
    const float* dt = (const float*)d_in[3];
    const float* Bm = (const float*)d_in[4];
    const float* Cm = (const float*)d_in[5];
    const float* Dv = (const float*)d_in[6];
    float* out = (float*)d_out;

    __half *uh, *fptr, *ysptr, *bop, *cop;
    cudaGetSymbolAddress((void**)&uh,    g_uh);
    cudaGetSymbolAddress((void**)&fptr,  g_fh);
    cudaGetSymbolAddress((void**)&ysptr, g_ysh);
    cudaGetSymbolAddress((void**)&bop,   g_BopH);
    cudaGetSymbolAddress((void**)&cop,   g_CopH);

    const int smem_pipe = 4 * STG * 2;              // 73728 (2 stages A+B)
    cudaFuncSetAttribute(gemm1_f16,
                         cudaFuncAttributeMaxDynamicSharedMemorySize, smem_pipe);
    cudaFuncSetAttribute(gemm2_f16,
                         cudaFuncAttributeMaxDynamicSharedMemorySize, smem_pipe);

    u2h_kernel<<<Mrows * 256 / (256 * 8), 256>>>(u);
    prep_kernel<<<256, 512>>>(Ad, Gd, dt, Bm, Cm);

    // GEMM1 + fused local scan: f = u @ Bop^T (fp16 out), chunk states -> g_cf
    gemm1_f16<<<dim3(4, 256), 256, smem_pipe>>>(uh, bop, fptr);

    scan_combine<<<256, 256>>>();

    // final scan: ys = scan(f), fp16 in/out, 4 chunks per thread
    scan_final4<<<Bc * NCHUNK / 4, 256>>>();

    // GEMM2: out = ys @ Cop^T + D*u (u fp16)
    gemm2_f16<<<dim3(2, 256), 256, smem_pipe>>>(ysptr, cop, out, uh, Dv);
}